// round 2
// baseline (speedup 1.0000x reference)
#include <cuda_runtime.h>
#include <cuda_bf16.h>

#define B_ 32
#define N_ 256

// Scratch (allocation-free rule: __device__ globals)
__device__ int g_cum[B_ * N_];
__device__ int g_total[B_];
__device__ int g_is64;

// ---------------------------------------------------------------------------
// Detect whether integer inputs are int64 or int32.
// durations values are in [0,16). If stored as int64 (little-endian), every
// odd 32-bit word of the first 64 elements is 0. If int32, the odd words are
// 64 random values in [0,16) — all-zero probability 16^-64.
// ---------------------------------------------------------------------------
__global__ void detect_kernel(const int* __restrict__ dur_raw) {
    int acc = 0;
#pragma unroll
    for (int i = 1; i < 128; i += 2) acc |= dur_raw[i];
    g_is64 = (acc == 0) ? 1 : 0;
}

// ---------------------------------------------------------------------------
// Per-batch inclusive scan of durations (N_=256). One block per batch.
// ---------------------------------------------------------------------------
__global__ void scan_kernel(const void* __restrict__ dur_raw) {
    __shared__ int s[N_];
    const int b = blockIdx.x;
    const int i = threadIdx.x;
    const int is64 = g_is64;
    int v;
    if (is64) {
        v = (int)((const long long*)dur_raw)[b * N_ + i];
    } else {
        v = ((const int*)dur_raw)[b * N_ + i];
    }
    s[i] = v;
    __syncthreads();
#pragma unroll
    for (int off = 1; off < N_; off <<= 1) {
        int add = (i >= off) ? s[i - off] : 0;
        __syncthreads();
        s[i] += add;
        __syncthreads();
    }
    g_cum[b * N_ + i] = s[i];
    if (i == N_ - 1) g_total[b] = s[i];
}

// ---------------------------------------------------------------------------
// Main kernel: one block per (frame t, batch b). 128 threads, float4 I/O.
// All control flow is block-uniform.
// ---------------------------------------------------------------------------
__global__ __launch_bounds__(128) void frame_kernel(
    const float4* __restrict__ start,
    const float4* __restrict__ mid,
    const float4* __restrict__ end,
    const void* __restrict__ dur_raw,
    const void* __restrict__ rc_raw,
    float4* __restrict__ out,
    float* __restrict__ mask_out,
    int T, int F4, int write_mask)
{
    const int t = blockIdx.x;
    const int b = blockIdx.y;
    const int tid = threadIdx.x;

    const int total = g_total[b];
    const bool active = (t < total);

    if (write_mask && tid == 0) {
        mask_out[(long long)b * T + t] = active ? 1.0f : 0.0f;
    }

    const long long outbase = ((long long)b * T + t) * (long long)F4;

    if (!active) {
        const float4 z = make_float4(0.f, 0.f, 0.f, 0.f);
        for (int f = tid; f < F4; f += 128) out[outbase + f] = z;
        return;
    }

    // upper_bound over cum[b][:]: first i with cum[i] > t  (searchsorted right)
    // Run bisection to convergence: needs 9 steps for n=256 (answers in [0,256]).
    const int* __restrict__ cum = g_cum + b * N_;
    int lo = 0, hi = N_;
    while (lo < hi) {
        int m = (lo + hi) >> 1;
        if (cum[m] <= t) lo = m + 1; else hi = m;
    }
    int idx = lo < (N_ - 1) ? lo : (N_ - 1);

    const int is64 = g_is64;
    int d, cls;
    if (is64) {
        d   = (int)((const long long*)dur_raw)[b * N_ + idx];
        cls = (int)((const long long*)rc_raw)[b * N_ + idx];
    } else {
        d   = ((const int*)dur_raw)[b * N_ + idx];
        cls = ((const int*)rc_raw)[b * N_ + idx];
    }
    const int off = cum[idx] - d;
    const int p = t - off;

    const bool is_first  = (p == 0) && (d > 1);
    const bool is_last   = (p == d - 1) && (d > 1);
    const int  half      = d >> 1;
    const bool in_first  = (p < half);
    const bool use_linear = (cls == 1) && (d >= 4);

    const float pf = (float)p;
    int den1 = half - 1;      if (den1 < 1) den1 = 1;
    int den2 = d - half - 1;  if (den2 < 1) den2 = 1;
    const float t1 = pf / (float)den1;
    const float t2 = (pf - (float)half) / (float)den2;

    const long long rowbase = ((long long)b * N_ + idx) * (long long)F4;

    if (use_linear) {
        const float4* __restrict__ A;
        const float4* __restrict__ Bv;
        float w1;
        if (in_first) {
            A = start + rowbase; Bv = mid + rowbase; w1 = t1;
        } else {
            A = mid + rowbase;   Bv = end + rowbase; w1 = t2;
        }
        const float w0 = 1.0f - w1;
        for (int f = tid; f < F4; f += 128) {
            float4 a = A[f], c = Bv[f], r;
            r.x = a.x * w0 + c.x * w1;
            r.y = a.y * w0 + c.y * w1;
            r.z = a.z * w0 + c.z * w1;
            r.w = a.w * w0 + c.w * w1;
            out[outbase + f] = r;
        }
    } else {
        // plateau: pick exactly one of the three rows (uniform across block)
        const float4* __restrict__ P =
            is_first ? (start + rowbase) : (is_last ? (end + rowbase) : (mid + rowbase));
        for (int f = tid; f < F4; f += 128) {
            out[outbase + f] = P[f];
        }
    }
}

// ---------------------------------------------------------------------------
// Launch
// ---------------------------------------------------------------------------
extern "C" void kernel_launch(void* const* d_in, const int* in_sizes, int n_in,
                              void* d_out, int out_size) {
    const float* start = (const float*)d_in[0];
    const float* mid   = (const float*)d_in[1];
    const float* end   = (const float*)d_in[2];
    const void*  dur   = d_in[3];
    const void*  rc    = d_in[4];

    const int BN = in_sizes[3];                 // B*N = 8192
    const int F  = in_sizes[0] / BN;            // 512
    const int F4 = F / 4;
    (void)n_in;

    // Derive T (max_frames) from out_size. Prefer the (out, mask) layout:
    // out_size = B*T*(F+1). Fall back to out-only layout B*T*F.
    long long os = (long long)out_size;
    int T;
    int write_mask;
    if (os % ((long long)B_ * (F + 1)) == 0) {
        T = (int)(os / ((long long)B_ * (F + 1)));
        write_mask = 1;
    } else {
        T = (int)(os / ((long long)B_ * F));
        write_mask = 0;
    }

    float* out_f  = (float*)d_out;
    float* mask_f = out_f + (long long)B_ * T * F;

    detect_kernel<<<1, 1>>>((const int*)dur);
    scan_kernel<<<B_, N_>>>(dur);
    dim3 grid(T, B_);
    frame_kernel<<<grid, 128>>>(
        (const float4*)start, (const float4*)mid, (const float4*)end,
        dur, rc, (float4*)out_f, mask_f, T, F4, write_mask);
}

// round 3
// speedup vs baseline: 1.2631x; 1.2631x over previous
#include <cuda_runtime.h>
#include <cuda_bf16.h>

#define B_ 32
#define N_ 256
#define META_CAP (1 << 20)   // supports B*T up to 1M frames

// Scratch (allocation-free rule: __device__ globals)
__device__ int  g_cum[B_ * N_];
__device__ int  g_is64;
__device__ int2 g_meta[META_CAP];   // .x = packed sel (-1 = inactive), .y = w1 bits

// ---------------------------------------------------------------------------
// Setup: per-batch inclusive scan of durations + int32/int64 detection.
// Detection reads only words [0, 512) of the raw buffer, which is in-bounds
// for both interpretations (int32: 8192 words; int64: 16384 words).
// durations < 16, so if int64, every odd word is 0; if int32, 256 random
// values in [0,16) are all zero with prob 16^-256.
// ---------------------------------------------------------------------------
__global__ void setup_kernel(const void* __restrict__ dur_raw) {
    __shared__ int s[N_];
    __shared__ int s_or[8];
    __shared__ int s_is64;
    const int b = blockIdx.x;
    const int i = threadIdx.x;

    const int* d32 = (const int*)dur_raw;
    int odd = d32[2 * i + 1];
    odd = __reduce_or_sync(0xffffffff, odd);
    if ((i & 31) == 0) s_or[i >> 5] = odd;
    __syncthreads();
    if (i == 0) {
        int acc = 0;
#pragma unroll
        for (int w = 0; w < 8; ++w) acc |= s_or[w];
        s_is64 = (acc == 0) ? 1 : 0;
        if (b == 0) g_is64 = s_is64;
    }
    __syncthreads();
    const int is64 = s_is64;

    int v = is64 ? (int)((const long long*)dur_raw)[b * N_ + i]
                 : d32[b * N_ + i];
    s[i] = v;
    __syncthreads();
#pragma unroll
    for (int off = 1; off < N_; off <<= 1) {
        int add = (i >= off) ? s[i - off] : 0;
        __syncthreads();
        s[i] += add;
        __syncthreads();
    }
    g_cum[b * N_ + i] = s[i];
}

// ---------------------------------------------------------------------------
// Meta: one thread per (b, t). Binary search over the smem-staged cum row,
// emit per-frame descriptor + coalesced mask.
//  sel: bits [0,8)=idx, [8,10)=A source (0=start,1=mid,2=end),
//       [10,12)=B source (3 = plateau/copy), -1 = inactive.
// ---------------------------------------------------------------------------
__global__ __launch_bounds__(256) void meta_kernel(
    const void* __restrict__ dur_raw,
    const void* __restrict__ rc_raw,
    float* __restrict__ mask_out,
    int T, int write_mask)
{
    __shared__ int cum_s[N_];
    const int b = blockIdx.y;
    const int t = blockIdx.x * 256 + threadIdx.x;
    if (threadIdx.x < N_) cum_s[threadIdx.x] = g_cum[b * N_ + threadIdx.x];
    __syncthreads();
    if (t >= T) return;

    const int total = cum_s[N_ - 1];
    const bool active = (t < total);
    if (write_mask) mask_out[(long long)b * T + t] = active ? 1.0f : 0.0f;

    int2 mv;
    if (!active) {
        mv.x = -1; mv.y = 0;
    } else {
        // upper_bound: first i with cum[i] > t
        int lo = 0, hi = N_;
        while (lo < hi) {
            int m = (lo + hi) >> 1;
            if (cum_s[m] <= t) lo = m + 1; else hi = m;
        }
        int idx = lo < (N_ - 1) ? lo : (N_ - 1);

        int d, cls;
        if (g_is64) {
            d   = (int)((const long long*)dur_raw)[b * N_ + idx];
            cls = (int)((const long long*)rc_raw)[b * N_ + idx];
        } else {
            d   = ((const int*)dur_raw)[b * N_ + idx];
            cls = ((const int*)rc_raw)[b * N_ + idx];
        }
        const int p = t - (cum_s[idx] - d);

        const bool is_first   = (p == 0) && (d > 1);
        const bool is_last    = (p == d - 1) && (d > 1);
        const int  half       = d >> 1;
        const bool use_linear = (cls == 1) && (d >= 4);

        int aS, bS;
        float w1 = 0.0f;
        if (use_linear) {
            if (p < half) {
                int den = half - 1; if (den < 1) den = 1;
                aS = 0; bS = 1; w1 = (float)p / (float)den;
            } else {
                int den = d - half - 1; if (den < 1) den = 1;
                aS = 1; bS = 2; w1 = (float)(p - half) / (float)den;
            }
        } else {
            aS = is_first ? 0 : (is_last ? 2 : 1);
            bS = 3;
        }
        mv.x = idx | (aS << 8) | (bS << 10);
        mv.y = __float_as_int(w1);
    }
    g_meta[(long long)b * T + t] = mv;
}

// ---------------------------------------------------------------------------
// Frame: pure streaming. 2 frames per 256-thread block; threads [0,128) do
// frame 0, [128,256) frame 1. All control is warp-uniform.
// ---------------------------------------------------------------------------
__global__ __launch_bounds__(256) void frame_kernel(
    const float4* __restrict__ start,
    const float4* __restrict__ mid,
    const float4* __restrict__ end,
    float4* __restrict__ out,
    int T, int F4)
{
    const int b  = blockIdx.y;
    const int fr = threadIdx.x >> 7;
    const int f0 = threadIdx.x & 127;
    const int t  = blockIdx.x * 2 + fr;
    if (t >= T) return;

    const int2 mv = g_meta[(long long)b * T + t];
    const long long outbase = ((long long)b * T + t) * (long long)F4;

    const int sel = mv.x;
    if (sel < 0) {
        const float4 z = make_float4(0.f, 0.f, 0.f, 0.f);
        for (int f = f0; f < F4; f += 128) out[outbase + f] = z;
        return;
    }

    const int idx = sel & 255;
    const int aS  = (sel >> 8) & 3;
    const int bS  = (sel >> 10) & 3;
    const long long rowbase = ((long long)b * N_ + idx) * (long long)F4;

    const float4* __restrict__ A =
        (aS == 0) ? (start + rowbase) : ((aS == 1) ? (mid + rowbase) : (end + rowbase));

    if (bS == 3) {
        for (int f = f0; f < F4; f += 128) out[outbase + f] = A[f];
    } else {
        const float4* __restrict__ Bv = (bS == 1) ? (mid + rowbase) : (end + rowbase);
        const float w1 = __int_as_float(mv.y);
        const float w0 = 1.0f - w1;
        for (int f = f0; f < F4; f += 128) {
            float4 a = A[f], c = Bv[f], r;
            r.x = fmaf(a.x, w0, c.x * w1);
            r.y = fmaf(a.y, w0, c.y * w1);
            r.z = fmaf(a.z, w0, c.z * w1);
            r.w = fmaf(a.w, w0, c.w * w1);
            out[outbase + f] = r;
        }
    }
}

// ---------------------------------------------------------------------------
// Launch
// ---------------------------------------------------------------------------
extern "C" void kernel_launch(void* const* d_in, const int* in_sizes, int n_in,
                              void* d_out, int out_size) {
    const float* start = (const float*)d_in[0];
    const float* mid   = (const float*)d_in[1];
    const float* end   = (const float*)d_in[2];
    const void*  dur   = d_in[3];
    const void*  rc    = d_in[4];
    (void)n_in;

    const int BN = in_sizes[3];                 // B*N = 8192
    const int F  = in_sizes[0] / BN;            // 512
    const int F4 = F / 4;

    // Derive T from out_size: (out, mask) layout -> B*T*(F+1); else B*T*F.
    long long os = (long long)out_size;
    int T, write_mask;
    if (os % ((long long)B_ * (F + 1)) == 0) {
        T = (int)(os / ((long long)B_ * (F + 1)));
        write_mask = 1;
    } else {
        T = (int)(os / ((long long)B_ * F));
        write_mask = 0;
    }

    float* out_f  = (float*)d_out;
    float* mask_f = out_f + (long long)B_ * T * F;

    setup_kernel<<<B_, N_>>>(dur);
    dim3 mgrid((T + 255) / 256, B_);
    meta_kernel<<<mgrid, 256>>>(dur, rc, mask_f, T, write_mask);
    dim3 fgrid((T + 1) / 2, B_);
    frame_kernel<<<fgrid, 256>>>(
        (const float4*)start, (const float4*)mid, (const float4*)end,
        (float4*)out_f, T, F4);
}

// round 4
// speedup vs baseline: 2.3606x; 1.8689x over previous
#include <cuda_runtime.h>
#include <cuda_bf16.h>

#define B_ 32
#define N_ 256
#define META_CAP (1 << 20)

// Scratch (allocation-free rule: __device__ global)
__device__ int2 g_meta[META_CAP];  // .x = packed sel (-1 = inactive), .y = w1 bits

// ---------------------------------------------------------------------------
// Meta: grid (ceil(T/256), B), 256 threads. Each block:
//  - detects int32 vs int64 (reads words [1,512) odd: in-bounds for both
//    interpretations; durations < 16 so int64 => all odd words 0)
//  - rebuilds the inclusive cumsum of its batch row in smem (cheap)
//  - binary-searches, emits per-frame descriptor + coalesced mask
// sel: bits [0,8)=idx, [8,10)=A source (0=s,1=m,2=e), [10,12)=B source (3=copy)
// ---------------------------------------------------------------------------
__global__ __launch_bounds__(256) void meta_kernel(
    const void* __restrict__ dur_raw,
    const void* __restrict__ rc_raw,
    float* __restrict__ mask_out,
    int T, int write_mask)
{
    __shared__ int cum_s[N_];
    __shared__ int s_is64;
    const int b   = blockIdx.y;
    const int tid = threadIdx.x;

    if (tid < 32) {
        const int* d32 = (const int*)dur_raw;
        int acc = 0;
#pragma unroll
        for (int i = tid; i < 256; i += 32) acc |= d32[2 * i + 1];
        acc = __reduce_or_sync(0xffffffff, acc);
        if (tid == 0) s_is64 = (acc == 0) ? 1 : 0;
    }
    __syncthreads();
    const int is64 = s_is64;

    int v = is64 ? (int)((const long long*)dur_raw)[b * N_ + tid]
                 : ((const int*)dur_raw)[b * N_ + tid];
    cum_s[tid] = v;
    __syncthreads();
#pragma unroll
    for (int off = 1; off < N_; off <<= 1) {
        int add = (tid >= off) ? cum_s[tid - off] : 0;
        __syncthreads();
        cum_s[tid] += add;
        __syncthreads();
    }

    const int t = blockIdx.x * 256 + tid;
    if (t >= T) return;

    const int total = cum_s[N_ - 1];
    const bool active = (t < total);
    if (write_mask) mask_out[(long long)b * T + t] = active ? 1.0f : 0.0f;

    int2 mv;
    if (!active) {
        mv.x = -1; mv.y = 0;
    } else {
        int lo = 0, hi = N_;
        while (lo < hi) {
            int m = (lo + hi) >> 1;
            if (cum_s[m] <= t) lo = m + 1; else hi = m;
        }
        int idx = lo < (N_ - 1) ? lo : (N_ - 1);

        const int d = cum_s[idx] - (idx ? cum_s[idx - 1] : 0);
        int cls = is64 ? (int)((const long long*)rc_raw)[b * N_ + idx]
                       : ((const int*)rc_raw)[b * N_ + idx];
        const int p = t - (cum_s[idx] - d);

        const bool is_first   = (p == 0) && (d > 1);
        const bool is_last    = (p == d - 1) && (d > 1);
        const int  half       = d >> 1;
        const bool use_linear = (cls == 1) && (d >= 4);

        int aS, bS;
        float w1 = 0.0f;
        if (use_linear) {
            if (p < half) {
                int den = half - 1; if (den < 1) den = 1;
                aS = 0; bS = 1; w1 = (float)p / (float)den;
            } else {
                int den = d - half - 1; if (den < 1) den = 1;
                aS = 1; bS = 2; w1 = (float)(p - half) / (float)den;
            }
        } else {
            aS = is_first ? 0 : (is_last ? 2 : 1);
            bS = 3;
        }
        mv.x = idx | (aS << 8) | (bS << 10);
        mv.y = __float_as_int(w1);
    }
    g_meta[(long long)b * T + t] = mv;
}

// ---------------------------------------------------------------------------
// Frame: 256-thread block = 2 groups x 128 threads; each group streams 4
// consecutive frames of one batch (MLP=4-8 per thread, L1 reuse across
// frames of the same segment). Phase 1: batched loads; phase 2: stores.
// All branches warp-uniform (a warp's threads share the same 4 frames).
// ---------------------------------------------------------------------------
__global__ __launch_bounds__(256) void frame_kernel(
    const float4* __restrict__ start,
    const float4* __restrict__ mid,
    const float4* __restrict__ end,
    float4* __restrict__ out,
    int T, int F4)
{
    __shared__ int2 meta_s[8];
    const int b     = blockIdx.y;
    const int grp   = threadIdx.x >> 7;     // 0 or 1
    const int f0    = threadIdx.x & 127;
    const int tbase = blockIdx.x * 8 + grp * 4;

    if (threadIdx.x < 8) {
        int tt = blockIdx.x * 8 + threadIdx.x;
        meta_s[threadIdx.x] = (tt < T) ? g_meta[(long long)b * T + tt]
                                       : make_int2(-1, 0);
    }
    __syncthreads();

    float4 av[4], bv[4];
    float  w1v[4];
    int    mode[4];                         // 0=zero, 1=copy, 2=lerp

#pragma unroll
    for (int k = 0; k < 4; ++k) {
        const int2 mv = meta_s[grp * 4 + k];
        const int sel = mv.x;
        if (sel < 0) {
            mode[k] = 0;
        } else {
            const int idx = sel & 255;
            const int aS  = (sel >> 8) & 3;
            const int bS  = (sel >> 10) & 3;
            const long long rb = ((long long)b * N_ + idx) * (long long)F4 + f0;
            const float4* __restrict__ A =
                (aS == 0) ? start : ((aS == 1) ? mid : end);
            av[k] = __ldg(A + rb);
            if (bS == 3) {
                mode[k] = 1;
            } else {
                const float4* __restrict__ Bp = (bS == 1) ? mid : end;
                bv[k]  = __ldg(Bp + rb);
                w1v[k] = __int_as_float(mv.y);
                mode[k] = 2;
            }
        }
    }

#pragma unroll
    for (int k = 0; k < 4; ++k) {
        const int t = tbase + k;
        if (t >= T) continue;
        const long long o = ((long long)b * T + t) * (long long)F4 + f0;
        float4 r;
        if (mode[k] == 0) {
            r = make_float4(0.f, 0.f, 0.f, 0.f);
        } else if (mode[k] == 1) {
            r = av[k];
        } else {
            const float w1 = w1v[k], w0 = 1.0f - w1;
            r.x = fmaf(av[k].x, w0, bv[k].x * w1);
            r.y = fmaf(av[k].y, w0, bv[k].y * w1);
            r.z = fmaf(av[k].z, w0, bv[k].z * w1);
            r.w = fmaf(av[k].w, w0, bv[k].w * w1);
        }
        __stcs(out + o, r);                 // streaming store: don't pollute L2
    }
}

// ---------------------------------------------------------------------------
// Launch
// ---------------------------------------------------------------------------
extern "C" void kernel_launch(void* const* d_in, const int* in_sizes, int n_in,
                              void* d_out, int out_size) {
    const float* start = (const float*)d_in[0];
    const float* mid   = (const float*)d_in[1];
    const float* end   = (const float*)d_in[2];
    const void*  dur   = d_in[3];
    const void*  rc    = d_in[4];
    (void)n_in;

    const int BN = in_sizes[3];                 // B*N
    const int F  = in_sizes[0] / BN;            // 512
    const int F4 = F / 4;

    long long os = (long long)out_size;
    int T, write_mask;
    if (os % ((long long)B_ * (F + 1)) == 0) {
        T = (int)(os / ((long long)B_ * (F + 1)));
        write_mask = 1;
    } else {
        T = (int)(os / ((long long)B_ * F));
        write_mask = 0;
    }

    float* out_f  = (float*)d_out;
    float* mask_f = out_f + (long long)B_ * T * F;

    dim3 mgrid((T + 255) / 256, B_);
    meta_kernel<<<mgrid, 256>>>(dur, rc, mask_f, T, write_mask);
    dim3 fgrid((T + 7) / 8, B_);
    frame_kernel<<<fgrid, 256>>>(
        (const float4*)start, (const float4*)mid, (const float4*)end,
        (float4*)out_f, T, F4);
}